// round 2
// baseline (speedup 1.0000x reference)
#include <cuda_runtime.h>
#include <math.h>

// Problem constants
#define BATCH 2
#define SEQ   2048
#define DMODEL 1024
#define NHEAD 16
#define HDIM  64
#define MTOT  (BATCH*SEQ)            // 4096
#define QKV_N (3*DMODEL)             // 3072
#define PER_TENSOR (MTOT*DMODEL)     // 4194304 floats per q/k/v tensor

// Scratch (allocation-free: __device__ globals)
__device__ float g_qkv[3u * 4194304u];   // [3][B][H][S][hd]
__device__ float g_attn[4194304u];       // [B][S][H*hd] == [4096][1024]

// ---------------------------------------------------------------------------
// GEMM 1: qkv = x @ w_qkv^T + b_qkv, scattered into [3][B][H][S][hd]
// A: [4096][1024] row-major (K contiguous), W: [3072][1024] row-major (K contig)
// 64x64 block tile, 256 threads, 4x4 per-thread microtile, K-step 16.
// ---------------------------------------------------------------------------
__global__ __launch_bounds__(256) void gemm_qkv_kernel(
    const float* __restrict__ A,
    const float* __restrict__ W,
    const float* __restrict__ bias)
{
    __shared__ float As[16][64];   // [k][m]
    __shared__ float Bs[16][64];   // [k][n]
    const int K = DMODEL;

    int tid = threadIdx.x;
    int tx = tid & 15;
    int ty = tid >> 4;
    int m0 = blockIdx.y * 64;
    int n0 = blockIdx.x * 64;

    int lrow = tid >> 2;           // 0..63
    int lk   = (tid & 3) * 4;      // 0,4,8,12

    const float* aPtr = A + (size_t)(m0 + lrow) * K + lk;
    const float* bPtr = W + (size_t)(n0 + lrow) * K + lk;

    float c[4][4];
#pragma unroll
    for (int i = 0; i < 4; i++)
#pragma unroll
        for (int j = 0; j < 4; j++) c[i][j] = 0.f;

    for (int kt = 0; kt < K; kt += 16) {
        float4 av = *(const float4*)(aPtr + kt);
        float4 bv = *(const float4*)(bPtr + kt);
        As[lk + 0][lrow] = av.x; As[lk + 1][lrow] = av.y;
        As[lk + 2][lrow] = av.z; As[lk + 3][lrow] = av.w;
        Bs[lk + 0][lrow] = bv.x; Bs[lk + 1][lrow] = bv.y;
        Bs[lk + 2][lrow] = bv.z; Bs[lk + 3][lrow] = bv.w;
        __syncthreads();
#pragma unroll
        for (int k = 0; k < 16; k++) {
            float4 a4 = *(const float4*)&As[k][ty * 4];
            float4 b4 = *(const float4*)&Bs[k][tx * 4];
            c[0][0] += a4.x * b4.x; c[0][1] += a4.x * b4.y; c[0][2] += a4.x * b4.z; c[0][3] += a4.x * b4.w;
            c[1][0] += a4.y * b4.x; c[1][1] += a4.y * b4.y; c[1][2] += a4.y * b4.z; c[1][3] += a4.y * b4.w;
            c[2][0] += a4.z * b4.x; c[2][1] += a4.z * b4.y; c[2][2] += a4.z * b4.z; c[2][3] += a4.z * b4.w;
            c[3][0] += a4.w * b4.x; c[3][1] += a4.w * b4.y; c[3][2] += a4.w * b4.z; c[3][3] += a4.w * b4.w;
        }
        __syncthreads();
    }

    // Epilogue: bias + scatter to [which][B][H][S][hd]
#pragma unroll
    for (int i = 0; i < 4; i++) {
        int m = m0 + ty * 4 + i;
        int b = m >> 11;            // /2048
        int s = m & 2047;
#pragma unroll
        for (int j = 0; j < 4; j++) {
            int n = n0 + tx * 4 + j;
            float v = c[i][j] + bias[n];
            int which = n >> 10;    // 0=q,1=k,2=v
            int r = n & 1023;
            int h = r >> 6;
            int d = r & 63;
            g_qkv[(size_t)which * 4194304u +
                  ((size_t)((b << 4) + h) * SEQ + s) * HDIM + d] = v;
        }
    }
}

// ---------------------------------------------------------------------------
// GEMM 3: out = attn @ w_proj^T + b_proj
// ---------------------------------------------------------------------------
__global__ __launch_bounds__(256) void gemm_proj_kernel(
    const float* __restrict__ W,
    const float* __restrict__ bias,
    float* __restrict__ out)
{
    __shared__ float As[16][64];
    __shared__ float Bs[16][64];
    const int K = DMODEL;

    int tid = threadIdx.x;
    int tx = tid & 15;
    int ty = tid >> 4;
    int m0 = blockIdx.y * 64;
    int n0 = blockIdx.x * 64;

    int lrow = tid >> 2;
    int lk   = (tid & 3) * 4;

    const float* aPtr = g_attn + (size_t)(m0 + lrow) * K + lk;
    const float* bPtr = W + (size_t)(n0 + lrow) * K + lk;

    float c[4][4];
#pragma unroll
    for (int i = 0; i < 4; i++)
#pragma unroll
        for (int j = 0; j < 4; j++) c[i][j] = 0.f;

    for (int kt = 0; kt < K; kt += 16) {
        float4 av = *(const float4*)(aPtr + kt);
        float4 bv = *(const float4*)(bPtr + kt);
        As[lk + 0][lrow] = av.x; As[lk + 1][lrow] = av.y;
        As[lk + 2][lrow] = av.z; As[lk + 3][lrow] = av.w;
        Bs[lk + 0][lrow] = bv.x; Bs[lk + 1][lrow] = bv.y;
        Bs[lk + 2][lrow] = bv.z; Bs[lk + 3][lrow] = bv.w;
        __syncthreads();
#pragma unroll
        for (int k = 0; k < 16; k++) {
            float4 a4 = *(const float4*)&As[k][ty * 4];
            float4 b4 = *(const float4*)&Bs[k][tx * 4];
            c[0][0] += a4.x * b4.x; c[0][1] += a4.x * b4.y; c[0][2] += a4.x * b4.z; c[0][3] += a4.x * b4.w;
            c[1][0] += a4.y * b4.x; c[1][1] += a4.y * b4.y; c[1][2] += a4.y * b4.z; c[1][3] += a4.y * b4.w;
            c[2][0] += a4.z * b4.x; c[2][1] += a4.z * b4.y; c[2][2] += a4.z * b4.z; c[2][3] += a4.z * b4.w;
            c[3][0] += a4.w * b4.x; c[3][1] += a4.w * b4.y; c[3][2] += a4.w * b4.z; c[3][3] += a4.w * b4.w;
        }
        __syncthreads();
    }

#pragma unroll
    for (int i = 0; i < 4; i++) {
        int m = m0 + ty * 4 + i;
#pragma unroll
        for (int j = 0; j < 4; j++) {
            int n = n0 + tx * 4 + j;
            out[(size_t)m * DMODEL + n] = c[i][j] + bias[n];
        }
    }
}

// ---------------------------------------------------------------------------
// Flash attention (fp32, online softmax).
// Grid: (32 q-tiles, 16 heads, 2 batch). 256 threads, 4x4 microtile over a
// 64x64 score tile; K loop over 32 key tiles of 64.
// Dynamic smem: QsT | KsT | Vs | Ps = 4 * 64*64 floats = 64 KB.
// ---------------------------------------------------------------------------
__global__ __launch_bounds__(256) void flash_kernel()
{
    extern __shared__ float sm[];
    float* QsT = sm;            // [d][row]   (transposed, scale folded in)
    float* KsT = sm + 4096;     // [d][col]
    float* Vs  = sm + 8192;     // [kc][d]
    float* Ps  = sm + 12288;    // [row][kc]

    int tid = threadIdx.x;
    int tx = tid & 15;
    int ty = tid >> 4;
    int qt = blockIdx.x;
    int h  = blockIdx.y;
    int b  = blockIdx.z;

    const float scale = 0.125f;   // 1/sqrt(64)

    const float* Qg = g_qkv + 0u * 4194304u + ((size_t)((b << 4) + h) * SEQ + qt * 64) * HDIM;
    const float* Kg = g_qkv + 1u * 4194304u + (size_t)((b << 4) + h) * SEQ * HDIM;
    const float* Vg = g_qkv + 2u * 4194304u + (size_t)((b << 4) + h) * SEQ * HDIM;

    // Load Q tile transposed, pre-scaled.
#pragma unroll
    for (int it = 0; it < 4; it++) {
        int idx = tid + it * 256;
        int row = idx >> 4;
        int d   = (idx & 15) * 4;
        float4 v = *(const float4*)(Qg + row * HDIM + d);
        QsT[(d + 0) * 64 + row] = v.x * scale;
        QsT[(d + 1) * 64 + row] = v.y * scale;
        QsT[(d + 2) * 64 + row] = v.z * scale;
        QsT[(d + 3) * 64 + row] = v.w * scale;
    }

    float m_i[4], l_i[4], o[4][4];
#pragma unroll
    for (int i = 0; i < 4; i++) {
        m_i[i] = -1e30f;
        l_i[i] = 0.f;
#pragma unroll
        for (int j = 0; j < 4; j++) o[i][j] = 0.f;
    }

    for (int kt = 0; kt < SEQ / 64; kt++) {
        const float* Kt = Kg + kt * 64 * HDIM;
        const float* Vt = Vg + kt * 64 * HDIM;
#pragma unroll
        for (int it = 0; it < 4; it++) {
            int idx = tid + it * 256;
            int row = idx >> 4;
            int d   = (idx & 15) * 4;
            float4 kv = *(const float4*)(Kt + row * HDIM + d);
            KsT[(d + 0) * 64 + row] = kv.x;
            KsT[(d + 1) * 64 + row] = kv.y;
            KsT[(d + 2) * 64 + row] = kv.z;
            KsT[(d + 3) * 64 + row] = kv.w;
            *(float4*)&Vs[row * HDIM + d] = *(const float4*)(Vt + row * HDIM + d);
        }
        __syncthreads();

        // S = (Q*scale) K^T
        float s_[4][4];
#pragma unroll
        for (int i = 0; i < 4; i++)
#pragma unroll
            for (int j = 0; j < 4; j++) s_[i][j] = 0.f;
#pragma unroll
        for (int kd = 0; kd < 64; kd++) {
            float4 a4 = *(const float4*)&QsT[kd * 64 + ty * 4];
            float4 b4 = *(const float4*)&KsT[kd * 64 + tx * 4];
            s_[0][0] += a4.x * b4.x; s_[0][1] += a4.x * b4.y; s_[0][2] += a4.x * b4.z; s_[0][3] += a4.x * b4.w;
            s_[1][0] += a4.y * b4.x; s_[1][1] += a4.y * b4.y; s_[1][2] += a4.y * b4.z; s_[1][3] += a4.y * b4.w;
            s_[2][0] += a4.z * b4.x; s_[2][1] += a4.z * b4.y; s_[2][2] += a4.z * b4.z; s_[2][3] += a4.z * b4.w;
            s_[3][0] += a4.w * b4.x; s_[3][1] += a4.w * b4.y; s_[3][2] += a4.w * b4.z; s_[3][3] += a4.w * b4.w;
        }

        // Online softmax per row (rows ty*4+i; 16 tx lanes hold 4 cols each)
#pragma unroll
        for (int i = 0; i < 4; i++) {
            float rm = fmaxf(fmaxf(s_[i][0], s_[i][1]), fmaxf(s_[i][2], s_[i][3]));
#pragma unroll
            for (int msk = 1; msk < 16; msk <<= 1)
                rm = fmaxf(rm, __shfl_xor_sync(0xffffffffu, rm, msk));
            float nm = fmaxf(m_i[i], rm);
            float alpha = __expf(m_i[i] - nm);
            m_i[i] = nm;
            float rs = 0.f;
#pragma unroll
            for (int j = 0; j < 4; j++) {
                s_[i][j] = __expf(s_[i][j] - nm);
                rs += s_[i][j];
            }
#pragma unroll
            for (int msk = 1; msk < 16; msk <<= 1)
                rs += __shfl_xor_sync(0xffffffffu, rs, msk);
            l_i[i] = l_i[i] * alpha + rs;
#pragma unroll
            for (int j = 0; j < 4; j++) o[i][j] *= alpha;
        }

        // Stage P in shared
#pragma unroll
        for (int i = 0; i < 4; i++)
#pragma unroll
            for (int j = 0; j < 4; j++)
                Ps[(ty * 4 + i) * 64 + tx * 4 + j] = s_[i][j];
        __syncthreads();

        // O += P @ V
#pragma unroll
        for (int kc = 0; kc < 64; kc++) {
            float4 b4 = *(const float4*)&Vs[kc * HDIM + tx * 4];
            float a0 = Ps[(ty * 4 + 0) * 64 + kc];
            float a1 = Ps[(ty * 4 + 1) * 64 + kc];
            float a2 = Ps[(ty * 4 + 2) * 64 + kc];
            float a3 = Ps[(ty * 4 + 3) * 64 + kc];
            o[0][0] += a0 * b4.x; o[0][1] += a0 * b4.y; o[0][2] += a0 * b4.z; o[0][3] += a0 * b4.w;
            o[1][0] += a1 * b4.x; o[1][1] += a1 * b4.y; o[1][2] += a1 * b4.z; o[1][3] += a1 * b4.w;
            o[2][0] += a2 * b4.x; o[2][1] += a2 * b4.y; o[2][2] += a2 * b4.z; o[2][3] += a2 * b4.w;
            o[3][0] += a3 * b4.x; o[3][1] += a3 * b4.y; o[3][2] += a3 * b4.z; o[3][3] += a3 * b4.w;
        }
        __syncthreads();
    }

    // Epilogue: normalize, write to [B][S][H*hd]
#pragma unroll
    for (int i = 0; i < 4; i++) {
        float inv = 1.0f / l_i[i];
        int s = qt * 64 + ty * 4 + i;
#pragma unroll
        for (int j = 0; j < 4; j++) {
            g_attn[((size_t)(b * SEQ + s)) * DMODEL + h * HDIM + tx * 4 + j] = o[i][j] * inv;
        }
    }
}

// ---------------------------------------------------------------------------
// Launch
// ---------------------------------------------------------------------------
extern "C" void kernel_launch(void* const* d_in, const int* in_sizes, int n_in,
                              void* d_out, int out_size)
{
    const float* x      = (const float*)d_in[0];
    const float* w_qkv  = (const float*)d_in[1];
    const float* b_qkv  = (const float*)d_in[2];
    const float* w_proj = (const float*)d_in[3];
    const float* b_proj = (const float*)d_in[4];
    float* out = (float*)d_out;

    cudaFuncSetAttribute(flash_kernel, cudaFuncAttributeMaxDynamicSharedMemorySize, 65536);

    gemm_qkv_kernel<<<dim3(QKV_N / 64, MTOT / 64), 256>>>(x, w_qkv, b_qkv);
    flash_kernel<<<dim3(SEQ / 64, NHEAD, BATCH), 256, 65536>>>();
    gemm_proj_kernel<<<dim3(DMODEL / 64, MTOT / 64), 256>>>(w_proj, b_proj, out);
}

// round 5
// speedup vs baseline: 1.4515x; 1.4515x over previous
#include <cuda_runtime.h>
#include <math.h>
#include <stdint.h>

// Problem constants
#define BATCH 2
#define SEQ   2048
#define DMODEL 1024
#define NHEAD 16
#define HDIM  64
#define MTOT  (BATCH*SEQ)            // 4096
#define QKV_N (3*DMODEL)             // 3072
#define GK    1024

// Scratch (allocation-free: __device__ globals)
__device__ float g_qkv[3u * 4194304u];   // [3][B][H][S][hd]
__device__ float g_attn[4194304u];       // [B][S][H*hd] == [4096][1024]

__device__ __forceinline__ float f32_to_tf32f(float x) {
    uint32_t r;
    asm("cvt.rna.tf32.f32 %0, %1;" : "=r"(r) : "f"(x));
    return __uint_as_float(r);
}

__device__ __forceinline__ void mma_tf32_16x8x8(float* c,
                                                float a0, float a1, float a2, float a3,
                                                float b0, float b1) {
    asm volatile(
        "mma.sync.aligned.m16n8k8.row.col.f32.tf32.tf32.f32 "
        "{%0,%1,%2,%3}, {%4,%5,%6,%7}, {%8,%9}, {%0,%1,%2,%3};"
        : "+f"(c[0]), "+f"(c[1]), "+f"(c[2]), "+f"(c[3])
        : "r"(__float_as_uint(a0)), "r"(__float_as_uint(a1)),
          "r"(__float_as_uint(a2)), "r"(__float_as_uint(a3)),
          "r"(__float_as_uint(b0)), "r"(__float_as_uint(b1)));
}

// ---------------------------------------------------------------------------
// tf32 mma.sync GEMM: C[M,N] = A[M,K] @ W[N,K]^T + bias, K = 1024.
// CTA 128x128, 8 warps (2x4), warp tile 64x32 (4x4 m16n8k8 tiles), K-tile 16,
// double-buffered smem with stride-20 padding.
// mode 0: A from arg, scatter into g_qkv layout.
// mode 1: A = g_attn (resolved DEVICE-side; __device__ symbols must not be
//         passed as host-side kernel args), plain write to out.
// ---------------------------------------------------------------------------
#define LDS_STRIDE 20

__global__ __launch_bounds__(256) void gemm_tc_kernel(
    const float* __restrict__ A_arg,
    const float* __restrict__ W,
    const float* __restrict__ bias,
    float* __restrict__ out,
    int mode)
{
    __shared__ float As[2][128 * LDS_STRIDE];
    __shared__ float Bs[2][128 * LDS_STRIDE];

    const float* A = (A_arg != nullptr) ? A_arg : (const float*)g_attn;

    int tid  = threadIdx.x;
    int wid  = tid >> 5;
    int lane = tid & 31;
    int wm   = wid >> 2;          // 0..1
    int wn   = wid & 3;           // 0..3
    int g    = lane >> 2;         // groupID 0..7
    int tig  = lane & 3;          // thread-in-group 0..3

    int m0 = blockIdx.y * 128;
    int n0 = blockIdx.x * 128;

    // global load coords: two float4 per matrix per tile per thread
    int ar0 = tid >> 2;           // row 0..63
    int ar1 = ar0 + 64;           // row 64..127
    int ac  = (tid & 3) * 4;      // col 0,4,8,12 within 16-wide k-tile

    const float* Ab = A + (size_t)m0 * GK + ac;
    const float* Wb = W + (size_t)n0 * GK + ac;

    float c[4][4][4];             // [mt][nt][frag]
#pragma unroll
    for (int i = 0; i < 4; i++)
#pragma unroll
        for (int j = 0; j < 4; j++)
#pragma unroll
            for (int q = 0; q < 4; q++) c[i][j][q] = 0.f;

    // prologue: tile 0 -> buffer 0
    {
        float4 a0 = *(const float4*)(Ab + (size_t)ar0 * GK);
        float4 a1 = *(const float4*)(Ab + (size_t)ar1 * GK);
        float4 b0 = *(const float4*)(Wb + (size_t)ar0 * GK);
        float4 b1 = *(const float4*)(Wb + (size_t)ar1 * GK);
        float* as = As[0]; float* bs = Bs[0];
        as[ar0 * LDS_STRIDE + ac + 0] = f32_to_tf32f(a0.x);
        as[ar0 * LDS_STRIDE + ac + 1] = f32_to_tf32f(a0.y);
        as[ar0 * LDS_STRIDE + ac + 2] = f32_to_tf32f(a0.z);
        as[ar0 * LDS_STRIDE + ac + 3] = f32_to_tf32f(a0.w);
        as[ar1 * LDS_STRIDE + ac + 0] = f32_to_tf32f(a1.x);
        as[ar1 * LDS_STRIDE + ac + 1] = f32_to_tf32f(a1.y);
        as[ar1 * LDS_STRIDE + ac + 2] = f32_to_tf32f(a1.z);
        as[ar1 * LDS_STRIDE + ac + 3] = f32_to_tf32f(a1.w);
        bs[ar0 * LDS_STRIDE + ac + 0] = f32_to_tf32f(b0.x);
        bs[ar0 * LDS_STRIDE + ac + 1] = f32_to_tf32f(b0.y);
        bs[ar0 * LDS_STRIDE + ac + 2] = f32_to_tf32f(b0.z);
        bs[ar0 * LDS_STRIDE + ac + 3] = f32_to_tf32f(b0.w);
        bs[ar1 * LDS_STRIDE + ac + 0] = f32_to_tf32f(b1.x);
        bs[ar1 * LDS_STRIDE + ac + 1] = f32_to_tf32f(b1.y);
        bs[ar1 * LDS_STRIDE + ac + 2] = f32_to_tf32f(b1.z);
        bs[ar1 * LDS_STRIDE + ac + 3] = f32_to_tf32f(b1.w);
    }
    __syncthreads();

    const int NT = GK / 16;       // 64 k-tiles
    for (int kt = 0; kt < NT; kt++) {
        int cur = kt & 1;
        float4 na0, na1, nb0, nb1;
        if (kt < NT - 1) {
            int ko = (kt + 1) * 16;
            na0 = *(const float4*)(Ab + (size_t)ar0 * GK + ko);
            na1 = *(const float4*)(Ab + (size_t)ar1 * GK + ko);
            nb0 = *(const float4*)(Wb + (size_t)ar0 * GK + ko);
            nb1 = *(const float4*)(Wb + (size_t)ar1 * GK + ko);
        }

        const float* as = As[cur];
        const float* bs = Bs[cur];
#pragma unroll
        for (int k8 = 0; k8 < 2; k8++) {
            int kc = k8 * 8 + tig;
            float af[4][4], bf[4][2];
#pragma unroll
            for (int mt = 0; mt < 4; mt++) {
                int r = wm * 64 + mt * 16 + g;
                af[mt][0] = as[(r + 0) * LDS_STRIDE + kc];
                af[mt][1] = as[(r + 8) * LDS_STRIDE + kc];
                af[mt][2] = as[(r + 0) * LDS_STRIDE + kc + 4];
                af[mt][3] = as[(r + 8) * LDS_STRIDE + kc + 4];
            }
#pragma unroll
            for (int nt = 0; nt < 4; nt++) {
                int r = wn * 32 + nt * 8 + g;
                bf[nt][0] = bs[r * LDS_STRIDE + kc];
                bf[nt][1] = bs[r * LDS_STRIDE + kc + 4];
            }
#pragma unroll
            for (int mt = 0; mt < 4; mt++)
#pragma unroll
                for (int nt = 0; nt < 4; nt++)
                    mma_tf32_16x8x8(c[mt][nt],
                                    af[mt][0], af[mt][1], af[mt][2], af[mt][3],
                                    bf[nt][0], bf[nt][1]);
        }
        __syncthreads();

        if (kt < NT - 1) {
            float* asn = As[cur ^ 1]; float* bsn = Bs[cur ^ 1];
            asn[ar0 * LDS_STRIDE + ac + 0] = f32_to_tf32f(na0.x);
            asn[ar0 * LDS_STRIDE + ac + 1] = f32_to_tf32f(na0.y);
            asn[ar0 * LDS_STRIDE + ac + 2] = f32_to_tf32f(na0.z);
            asn[ar0 * LDS_STRIDE + ac + 3] = f32_to_tf32f(na0.w);
            asn[ar1 * LDS_STRIDE + ac + 0] = f32_to_tf32f(na1.x);
            asn[ar1 * LDS_STRIDE + ac + 1] = f32_to_tf32f(na1.y);
            asn[ar1 * LDS_STRIDE + ac + 2] = f32_to_tf32f(na1.z);
            asn[ar1 * LDS_STRIDE + ac + 3] = f32_to_tf32f(na1.w);
            bsn[ar0 * LDS_STRIDE + ac + 0] = f32_to_tf32f(nb0.x);
            bsn[ar0 * LDS_STRIDE + ac + 1] = f32_to_tf32f(nb0.y);
            bsn[ar0 * LDS_STRIDE + ac + 2] = f32_to_tf32f(nb0.z);
            bsn[ar0 * LDS_STRIDE + ac + 3] = f32_to_tf32f(nb0.w);
            bsn[ar1 * LDS_STRIDE + ac + 0] = f32_to_tf32f(nb1.x);
            bsn[ar1 * LDS_STRIDE + ac + 1] = f32_to_tf32f(nb1.y);
            bsn[ar1 * LDS_STRIDE + ac + 2] = f32_to_tf32f(nb1.z);
            bsn[ar1 * LDS_STRIDE + ac + 3] = f32_to_tf32f(nb1.w);
            __syncthreads();
        }
    }

    // Epilogue: fragment layout c0,c1 @ (row g, col 2*tig), c2,c3 @ (row g+8)
#pragma unroll
    for (int mt = 0; mt < 4; mt++) {
#pragma unroll
        for (int half = 0; half < 2; half++) {
            int m = m0 + wm * 64 + mt * 16 + g + half * 8;
            int b = m >> 11;
            int s = m & 2047;
#pragma unroll
            for (int nt = 0; nt < 4; nt++) {
                int n = n0 + wn * 32 + nt * 8 + 2 * tig;
                float2 v;
                v.x = c[mt][nt][half * 2 + 0] + bias[n + 0];
                v.y = c[mt][nt][half * 2 + 1] + bias[n + 1];
                if (mode == 0) {
                    int which = n >> 10;
                    int rr = n & 1023;
                    int h = rr >> 6;
                    int d = rr & 63;
                    *(float2*)&g_qkv[(size_t)which * 4194304u +
                                     ((size_t)((b << 4) + h) * SEQ + s) * HDIM + d] = v;
                } else {
                    *(float2*)&out[(size_t)m * DMODEL + n] = v;
                }
            }
        }
    }
}

// ---------------------------------------------------------------------------
// Flash attention (fp32, online softmax) — unchanged from R2 passing version.
// ---------------------------------------------------------------------------
__global__ __launch_bounds__(256) void flash_kernel()
{
    extern __shared__ float smf[];
    float* QsT = smf;           // [d][row]
    float* KsT = smf + 4096;    // [d][col]
    float* Vs  = smf + 8192;    // [kc][d]
    float* Ps  = smf + 12288;   // [row][kc]

    int tid = threadIdx.x;
    int tx = tid & 15;
    int ty = tid >> 4;
    int qt = blockIdx.x;
    int h  = blockIdx.y;
    int b  = blockIdx.z;

    const float scale = 0.125f;

    const float* Qg = g_qkv + 0u * 4194304u + ((size_t)((b << 4) + h) * SEQ + qt * 64) * HDIM;
    const float* Kg = g_qkv + 1u * 4194304u + (size_t)((b << 4) + h) * SEQ * HDIM;
    const float* Vg = g_qkv + 2u * 4194304u + (size_t)((b << 4) + h) * SEQ * HDIM;

#pragma unroll
    for (int it = 0; it < 4; it++) {
        int idx = tid + it * 256;
        int row = idx >> 4;
        int d   = (idx & 15) * 4;
        float4 v = *(const float4*)(Qg + row * HDIM + d);
        QsT[(d + 0) * 64 + row] = v.x * scale;
        QsT[(d + 1) * 64 + row] = v.y * scale;
        QsT[(d + 2) * 64 + row] = v.z * scale;
        QsT[(d + 3) * 64 + row] = v.w * scale;
    }

    float m_i[4], l_i[4], o[4][4];
#pragma unroll
    for (int i = 0; i < 4; i++) {
        m_i[i] = -1e30f;
        l_i[i] = 0.f;
#pragma unroll
        for (int j = 0; j < 4; j++) o[i][j] = 0.f;
    }

    for (int kt = 0; kt < SEQ / 64; kt++) {
        const float* Kt = Kg + kt * 64 * HDIM;
        const float* Vt = Vg + kt * 64 * HDIM;
#pragma unroll
        for (int it = 0; it < 4; it++) {
            int idx = tid + it * 256;
            int row = idx >> 4;
            int d   = (idx & 15) * 4;
            float4 kv = *(const float4*)(Kt + row * HDIM + d);
            KsT[(d + 0) * 64 + row] = kv.x;
            KsT[(d + 1) * 64 + row] = kv.y;
            KsT[(d + 2) * 64 + row] = kv.z;
            KsT[(d + 3) * 64 + row] = kv.w;
            *(float4*)&Vs[row * HDIM + d] = *(const float4*)(Vt + row * HDIM + d);
        }
        __syncthreads();

        float s_[4][4];
#pragma unroll
        for (int i = 0; i < 4; i++)
#pragma unroll
            for (int j = 0; j < 4; j++) s_[i][j] = 0.f;
#pragma unroll
        for (int kd = 0; kd < 64; kd++) {
            float4 a4 = *(const float4*)&QsT[kd * 64 + ty * 4];
            float4 b4 = *(const float4*)&KsT[kd * 64 + tx * 4];
            s_[0][0] += a4.x * b4.x; s_[0][1] += a4.x * b4.y; s_[0][2] += a4.x * b4.z; s_[0][3] += a4.x * b4.w;
            s_[1][0] += a4.y * b4.x; s_[1][1] += a4.y * b4.y; s_[1][2] += a4.y * b4.z; s_[1][3] += a4.y * b4.w;
            s_[2][0] += a4.z * b4.x; s_[2][1] += a4.z * b4.y; s_[2][2] += a4.z * b4.z; s_[2][3] += a4.z * b4.w;
            s_[3][0] += a4.w * b4.x; s_[3][1] += a4.w * b4.y; s_[3][2] += a4.w * b4.z; s_[3][3] += a4.w * b4.w;
        }

#pragma unroll
        for (int i = 0; i < 4; i++) {
            float rm = fmaxf(fmaxf(s_[i][0], s_[i][1]), fmaxf(s_[i][2], s_[i][3]));
#pragma unroll
            for (int msk = 1; msk < 16; msk <<= 1)
                rm = fmaxf(rm, __shfl_xor_sync(0xffffffffu, rm, msk));
            float nm = fmaxf(m_i[i], rm);
            float alpha = __expf(m_i[i] - nm);
            m_i[i] = nm;
            float rs = 0.f;
#pragma unroll
            for (int j = 0; j < 4; j++) {
                s_[i][j] = __expf(s_[i][j] - nm);
                rs += s_[i][j];
            }
#pragma unroll
            for (int msk = 1; msk < 16; msk <<= 1)
                rs += __shfl_xor_sync(0xffffffffu, rs, msk);
            l_i[i] = l_i[i] * alpha + rs;
#pragma unroll
            for (int j = 0; j < 4; j++) o[i][j] *= alpha;
        }

#pragma unroll
        for (int i = 0; i < 4; i++)
#pragma unroll
            for (int j = 0; j < 4; j++)
                Ps[(ty * 4 + i) * 64 + tx * 4 + j] = s_[i][j];
        __syncthreads();

#pragma unroll
        for (int kc = 0; kc < 64; kc++) {
            float4 b4 = *(const float4*)&Vs[kc * HDIM + tx * 4];
            float a0 = Ps[(ty * 4 + 0) * 64 + kc];
            float a1 = Ps[(ty * 4 + 1) * 64 + kc];
            float a2 = Ps[(ty * 4 + 2) * 64 + kc];
            float a3 = Ps[(ty * 4 + 3) * 64 + kc];
            o[0][0] += a0 * b4.x; o[0][1] += a0 * b4.y; o[0][2] += a0 * b4.z; o[0][3] += a0 * b4.w;
            o[1][0] += a1 * b4.x; o[1][1] += a1 * b4.y; o[1][2] += a1 * b4.z; o[1][3] += a1 * b4.w;
            o[2][0] += a2 * b4.x; o[2][1] += a2 * b4.y; o[2][2] += a2 * b4.z; o[2][3] += a2 * b4.w;
            o[3][0] += a3 * b4.x; o[3][1] += a3 * b4.y; o[3][2] += a3 * b4.z; o[3][3] += a3 * b4.w;
        }
        __syncthreads();
    }

#pragma unroll
    for (int i = 0; i < 4; i++) {
        float inv = 1.0f / l_i[i];
        int s = qt * 64 + ty * 4 + i;
#pragma unroll
        for (int j = 0; j < 4; j++) {
            g_attn[((size_t)(b * SEQ + s)) * DMODEL + h * HDIM + tx * 4 + j] = o[i][j] * inv;
        }
    }
}

// ---------------------------------------------------------------------------
// Launch
// ---------------------------------------------------------------------------
extern "C" void kernel_launch(void* const* d_in, const int* in_sizes, int n_in,
                              void* d_out, int out_size)
{
    const float* x      = (const float*)d_in[0];
    const float* w_qkv  = (const float*)d_in[1];
    const float* b_qkv  = (const float*)d_in[2];
    const float* w_proj = (const float*)d_in[3];
    const float* b_proj = (const float*)d_in[4];
    float* out = (float*)d_out;

    cudaFuncSetAttribute(flash_kernel, cudaFuncAttributeMaxDynamicSharedMemorySize, 65536);

    gemm_tc_kernel<<<dim3(QKV_N / 128, MTOT / 128), 256>>>(x, w_qkv, b_qkv, nullptr, 0);
    flash_kernel<<<dim3(SEQ / 64, NHEAD, BATCH), 256, 65536>>>();
    // mode 1: A resolved device-side to g_attn (never pass __device__ symbol from host)
    gemm_tc_kernel<<<dim3(DMODEL / 128, MTOT / 128), 256>>>(nullptr, w_proj, b_proj, out, 1);
}

// round 6
// speedup vs baseline: 2.7704x; 1.9087x over previous
#include <cuda_runtime.h>
#include <math.h>
#include <stdint.h>

// Problem constants
#define BATCH 2
#define SEQ   2048
#define DMODEL 1024
#define NHEAD 16
#define HDIM  64
#define MTOT  (BATCH*SEQ)            // 4096
#define QKV_N (3*DMODEL)             // 3072
#define GK    1024

// Scratch (allocation-free: __device__ globals)
__device__ float g_qkv[3u * 4194304u];   // [3][B][H][S][hd]
__device__ float g_attn[4194304u];       // [B][S][H*hd] == [4096][1024]

__device__ __forceinline__ float f32_to_tf32f(float x) {
    uint32_t r;
    asm("cvt.rna.tf32.f32 %0, %1;" : "=r"(r) : "f"(x));
    return __uint_as_float(r);
}

__device__ __forceinline__ void mma_tf32_16x8x8(float* c,
                                                float a0, float a1, float a2, float a3,
                                                float b0, float b1) {
    asm volatile(
        "mma.sync.aligned.m16n8k8.row.col.f32.tf32.tf32.f32 "
        "{%0,%1,%2,%3}, {%4,%5,%6,%7}, {%8,%9}, {%0,%1,%2,%3};"
        : "+f"(c[0]), "+f"(c[1]), "+f"(c[2]), "+f"(c[3])
        : "r"(__float_as_uint(a0)), "r"(__float_as_uint(a1)),
          "r"(__float_as_uint(a2)), "r"(__float_as_uint(a3)),
          "r"(__float_as_uint(b0)), "r"(__float_as_uint(b1)));
}

// ---------------------------------------------------------------------------
// tf32 mma.sync GEMM (unchanged from R5 passing version).
// ---------------------------------------------------------------------------
#define LDS_STRIDE 20

__global__ __launch_bounds__(256) void gemm_tc_kernel(
    const float* __restrict__ A_arg,
    const float* __restrict__ W,
    const float* __restrict__ bias,
    float* __restrict__ out,
    int mode)
{
    __shared__ float As[2][128 * LDS_STRIDE];
    __shared__ float Bs[2][128 * LDS_STRIDE];

    const float* A = (A_arg != nullptr) ? A_arg : (const float*)g_attn;

    int tid  = threadIdx.x;
    int wid  = tid >> 5;
    int lane = tid & 31;
    int wm   = wid >> 2;
    int wn   = wid & 3;
    int g    = lane >> 2;
    int tig  = lane & 3;

    int m0 = blockIdx.y * 128;
    int n0 = blockIdx.x * 128;

    int ar0 = tid >> 2;
    int ar1 = ar0 + 64;
    int ac  = (tid & 3) * 4;

    const float* Ab = A + (size_t)m0 * GK + ac;
    const float* Wb = W + (size_t)n0 * GK + ac;

    float c[4][4][4];
#pragma unroll
    for (int i = 0; i < 4; i++)
#pragma unroll
        for (int j = 0; j < 4; j++)
#pragma unroll
            for (int q = 0; q < 4; q++) c[i][j][q] = 0.f;

    {
        float4 a0 = *(const float4*)(Ab + (size_t)ar0 * GK);
        float4 a1 = *(const float4*)(Ab + (size_t)ar1 * GK);
        float4 b0 = *(const float4*)(Wb + (size_t)ar0 * GK);
        float4 b1 = *(const float4*)(Wb + (size_t)ar1 * GK);
        float* as = As[0]; float* bs = Bs[0];
        as[ar0 * LDS_STRIDE + ac + 0] = f32_to_tf32f(a0.x);
        as[ar0 * LDS_STRIDE + ac + 1] = f32_to_tf32f(a0.y);
        as[ar0 * LDS_STRIDE + ac + 2] = f32_to_tf32f(a0.z);
        as[ar0 * LDS_STRIDE + ac + 3] = f32_to_tf32f(a0.w);
        as[ar1 * LDS_STRIDE + ac + 0] = f32_to_tf32f(a1.x);
        as[ar1 * LDS_STRIDE + ac + 1] = f32_to_tf32f(a1.y);
        as[ar1 * LDS_STRIDE + ac + 2] = f32_to_tf32f(a1.z);
        as[ar1 * LDS_STRIDE + ac + 3] = f32_to_tf32f(a1.w);
        bs[ar0 * LDS_STRIDE + ac + 0] = f32_to_tf32f(b0.x);
        bs[ar0 * LDS_STRIDE + ac + 1] = f32_to_tf32f(b0.y);
        bs[ar0 * LDS_STRIDE + ac + 2] = f32_to_tf32f(b0.z);
        bs[ar0 * LDS_STRIDE + ac + 3] = f32_to_tf32f(b0.w);
        bs[ar1 * LDS_STRIDE + ac + 0] = f32_to_tf32f(b1.x);
        bs[ar1 * LDS_STRIDE + ac + 1] = f32_to_tf32f(b1.y);
        bs[ar1 * LDS_STRIDE + ac + 2] = f32_to_tf32f(b1.z);
        bs[ar1 * LDS_STRIDE + ac + 3] = f32_to_tf32f(b1.w);
    }
    __syncthreads();

    const int NT = GK / 16;
    for (int kt = 0; kt < NT; kt++) {
        int cur = kt & 1;
        float4 na0, na1, nb0, nb1;
        if (kt < NT - 1) {
            int ko = (kt + 1) * 16;
            na0 = *(const float4*)(Ab + (size_t)ar0 * GK + ko);
            na1 = *(const float4*)(Ab + (size_t)ar1 * GK + ko);
            nb0 = *(const float4*)(Wb + (size_t)ar0 * GK + ko);
            nb1 = *(const float4*)(Wb + (size_t)ar1 * GK + ko);
        }

        const float* as = As[cur];
        const float* bs = Bs[cur];
#pragma unroll
        for (int k8 = 0; k8 < 2; k8++) {
            int kc = k8 * 8 + tig;
            float af[4][4], bf[4][2];
#pragma unroll
            for (int mt = 0; mt < 4; mt++) {
                int r = wm * 64 + mt * 16 + g;
                af[mt][0] = as[(r + 0) * LDS_STRIDE + kc];
                af[mt][1] = as[(r + 8) * LDS_STRIDE + kc];
                af[mt][2] = as[(r + 0) * LDS_STRIDE + kc + 4];
                af[mt][3] = as[(r + 8) * LDS_STRIDE + kc + 4];
            }
#pragma unroll
            for (int nt = 0; nt < 4; nt++) {
                int r = wn * 32 + nt * 8 + g;
                bf[nt][0] = bs[r * LDS_STRIDE + kc];
                bf[nt][1] = bs[r * LDS_STRIDE + kc + 4];
            }
#pragma unroll
            for (int mt = 0; mt < 4; mt++)
#pragma unroll
                for (int nt = 0; nt < 4; nt++)
                    mma_tf32_16x8x8(c[mt][nt],
                                    af[mt][0], af[mt][1], af[mt][2], af[mt][3],
                                    bf[nt][0], bf[nt][1]);
        }
        __syncthreads();

        if (kt < NT - 1) {
            float* asn = As[cur ^ 1]; float* bsn = Bs[cur ^ 1];
            asn[ar0 * LDS_STRIDE + ac + 0] = f32_to_tf32f(na0.x);
            asn[ar0 * LDS_STRIDE + ac + 1] = f32_to_tf32f(na0.y);
            asn[ar0 * LDS_STRIDE + ac + 2] = f32_to_tf32f(na0.z);
            asn[ar0 * LDS_STRIDE + ac + 3] = f32_to_tf32f(na0.w);
            asn[ar1 * LDS_STRIDE + ac + 0] = f32_to_tf32f(na1.x);
            asn[ar1 * LDS_STRIDE + ac + 1] = f32_to_tf32f(na1.y);
            asn[ar1 * LDS_STRIDE + ac + 2] = f32_to_tf32f(na1.z);
            asn[ar1 * LDS_STRIDE + ac + 3] = f32_to_tf32f(na1.w);
            bsn[ar0 * LDS_STRIDE + ac + 0] = f32_to_tf32f(nb0.x);
            bsn[ar0 * LDS_STRIDE + ac + 1] = f32_to_tf32f(nb0.y);
            bsn[ar0 * LDS_STRIDE + ac + 2] = f32_to_tf32f(nb0.z);
            bsn[ar0 * LDS_STRIDE + ac + 3] = f32_to_tf32f(nb0.w);
            bsn[ar1 * LDS_STRIDE + ac + 0] = f32_to_tf32f(nb1.x);
            bsn[ar1 * LDS_STRIDE + ac + 1] = f32_to_tf32f(nb1.y);
            bsn[ar1 * LDS_STRIDE + ac + 2] = f32_to_tf32f(nb1.z);
            bsn[ar1 * LDS_STRIDE + ac + 3] = f32_to_tf32f(nb1.w);
            __syncthreads();
        }
    }

#pragma unroll
    for (int mt = 0; mt < 4; mt++) {
#pragma unroll
        for (int half = 0; half < 2; half++) {
            int m = m0 + wm * 64 + mt * 16 + g + half * 8;
            int b = m >> 11;
            int s = m & 2047;
#pragma unroll
            for (int nt = 0; nt < 4; nt++) {
                int n = n0 + wn * 32 + nt * 8 + 2 * tig;
                float2 v;
                v.x = c[mt][nt][half * 2 + 0] + bias[n + 0];
                v.y = c[mt][nt][half * 2 + 1] + bias[n + 1];
                if (mode == 0) {
                    int which = n >> 10;
                    int rr = n & 1023;
                    int h = rr >> 6;
                    int d = rr & 63;
                    *(float2*)&g_qkv[(size_t)which * 4194304u +
                                     ((size_t)((b << 4) + h) * SEQ + s) * HDIM + d] = v;
                } else {
                    *(float2*)&out[(size_t)m * DMODEL + n] = v;
                }
            }
        }
    }
}

// ---------------------------------------------------------------------------
// Flash attention with tf32 mma.sync.
// CTA: 128 Q-rows; 8 warps, each owns 16 Q-rows (full score row per warp).
// Per 64-key tile: S = Q·K^T (mma, Q frags register-resident), online softmax
// in registers (intra-quad shuffles), P staged tf32 in per-warp Ps slab
// (__syncwarp only), O += P·V (mma).
// Smem floats: Ks[64][68] | Vs[64][72] | Ps[128][68]  = 70656 bytes.
// ---------------------------------------------------------------------------
#define KS_STRIDE 68
#define VS_STRIDE 72
#define PS_STRIDE 68
#define FLASH_SMEM ((64*KS_STRIDE + 64*VS_STRIDE + 128*PS_STRIDE) * 4)

__global__ __launch_bounds__(256) void flash_tc_kernel()
{
    extern __shared__ float smf[];
    float* Ks = smf;                                    // [64][KS_STRIDE]
    float* Vs = smf + 64 * KS_STRIDE;                   // [64][VS_STRIDE]
    float* Ps = smf + 64 * KS_STRIDE + 64 * VS_STRIDE;  // [128][PS_STRIDE]

    int tid  = threadIdx.x;
    int w    = tid >> 5;
    int lane = tid & 31;
    int g    = lane >> 2;          // 0..7
    int tig  = lane & 3;           // 0..3

    int q0 = blockIdx.x * 128;
    int h  = blockIdx.y;
    int b  = blockIdx.z;

    const float scale = 0.125f;    // 1/sqrt(64)

    const float* Qg = g_qkv + 0u * 4194304u + (size_t)((b << 4) + h) * SEQ * HDIM;
    const float* Kg = g_qkv + 1u * 4194304u + (size_t)((b << 4) + h) * SEQ * HDIM;
    const float* Vg = g_qkv + 2u * 4194304u + (size_t)((b << 4) + h) * SEQ * HDIM;

    // Q fragments, register-resident for whole kernel (scale + tf32 folded)
    int qrow = q0 + w * 16;
    float qf[8][4];
#pragma unroll
    for (int kc = 0; kc < 8; kc++) {
        int d0 = kc * 8 + tig;
        qf[kc][0] = f32_to_tf32f(Qg[(size_t)(qrow + g)     * HDIM + d0]     * scale);
        qf[kc][1] = f32_to_tf32f(Qg[(size_t)(qrow + g + 8) * HDIM + d0]     * scale);
        qf[kc][2] = f32_to_tf32f(Qg[(size_t)(qrow + g)     * HDIM + d0 + 4] * scale);
        qf[kc][3] = f32_to_tf32f(Qg[(size_t)(qrow + g + 8) * HDIM + d0 + 4] * scale);
    }

    float m0r = -1e30f, m1r = -1e30f, l0r = 0.f, l1r = 0.f;
    float ov[8][4];
#pragma unroll
    for (int nt = 0; nt < 8; nt++)
#pragma unroll
        for (int q = 0; q < 4; q++) ov[nt][q] = 0.f;

    float* Psw = Ps + w * 16 * PS_STRIDE;   // per-warp private slab

    for (int kt = 0; kt < SEQ / 64; kt++) {
        const float* Kt = Kg + (size_t)kt * 64 * HDIM;
        const float* Vt = Vg + (size_t)kt * 64 * HDIM;

        // Load + convert K and V tiles (aligned float4 paths)
#pragma unroll
        for (int it = 0; it < 4; it++) {
            int j   = tid + it * 256;          // float4 index 0..1023
            int row = j >> 4;
            int c4  = (j & 15) << 2;
            float4 kv = *(const float4*)(Kt + row * HDIM + c4);
            float4 vv = *(const float4*)(Vt + row * HDIM + c4);
            float4 kc4, vc4;
            kc4.x = f32_to_tf32f(kv.x); kc4.y = f32_to_tf32f(kv.y);
            kc4.z = f32_to_tf32f(kv.z); kc4.w = f32_to_tf32f(kv.w);
            vc4.x = f32_to_tf32f(vv.x); vc4.y = f32_to_tf32f(vv.y);
            vc4.z = f32_to_tf32f(vv.z); vc4.w = f32_to_tf32f(vv.w);
            *(float4*)&Ks[row * KS_STRIDE + c4] = kc4;
            *(float4*)&Vs[row * VS_STRIDE + c4] = vc4;
        }
        __syncthreads();

        // S = Q K^T  (per warp: 16 rows x 64 keys, 8 nt x 8 kc mma)
        float sc[8][4];
#pragma unroll
        for (int nt = 0; nt < 8; nt++)
#pragma unroll
            for (int q = 0; q < 4; q++) sc[nt][q] = 0.f;
#pragma unroll
        for (int kc = 0; kc < 8; kc++) {
            int d0 = kc * 8 + tig;
#pragma unroll
            for (int nt = 0; nt < 8; nt++) {
                int key = nt * 8 + g;
                float b0 = Ks[key * KS_STRIDE + d0];
                float b1 = Ks[key * KS_STRIDE + d0 + 4];
                mma_tf32_16x8x8(sc[nt], qf[kc][0], qf[kc][1], qf[kc][2], qf[kc][3], b0, b1);
            }
        }

        // Online softmax. Row r0 = qrow+g holds sc[nt][0],sc[nt][1];
        // row r1 = qrow+g+8 holds sc[nt][2],sc[nt][3]. Quad lanes (tig) share rows.
        float rm0 = -1e30f, rm1 = -1e30f;
#pragma unroll
        for (int nt = 0; nt < 8; nt++) {
            rm0 = fmaxf(rm0, fmaxf(sc[nt][0], sc[nt][1]));
            rm1 = fmaxf(rm1, fmaxf(sc[nt][2], sc[nt][3]));
        }
        rm0 = fmaxf(rm0, __shfl_xor_sync(0xffffffffu, rm0, 1));
        rm0 = fmaxf(rm0, __shfl_xor_sync(0xffffffffu, rm0, 2));
        rm1 = fmaxf(rm1, __shfl_xor_sync(0xffffffffu, rm1, 1));
        rm1 = fmaxf(rm1, __shfl_xor_sync(0xffffffffu, rm1, 2));

        float nm0 = fmaxf(m0r, rm0);
        float nm1 = fmaxf(m1r, rm1);
        float alpha0 = __expf(m0r - nm0);
        float alpha1 = __expf(m1r - nm1);
        m0r = nm0; m1r = nm1;

        float rs0 = 0.f, rs1 = 0.f;
#pragma unroll
        for (int nt = 0; nt < 8; nt++) {
            sc[nt][0] = __expf(sc[nt][0] - nm0);
            sc[nt][1] = __expf(sc[nt][1] - nm0);
            sc[nt][2] = __expf(sc[nt][2] - nm1);
            sc[nt][3] = __expf(sc[nt][3] - nm1);
            rs0 += sc[nt][0] + sc[nt][1];
            rs1 += sc[nt][2] + sc[nt][3];
        }
        rs0 += __shfl_xor_sync(0xffffffffu, rs0, 1);
        rs0 += __shfl_xor_sync(0xffffffffu, rs0, 2);
        rs1 += __shfl_xor_sync(0xffffffffu, rs1, 1);
        rs1 += __shfl_xor_sync(0xffffffffu, rs1, 2);
        l0r = l0r * alpha0 + rs0;
        l1r = l1r * alpha1 + rs1;

        // Rescale O accumulators
#pragma unroll
        for (int nt = 0; nt < 8; nt++) {
            ov[nt][0] *= alpha0; ov[nt][1] *= alpha0;
            ov[nt][2] *= alpha1; ov[nt][3] *= alpha1;
        }

        // Stage P (tf32-rounded) into per-warp slab; only this warp touches it.
#pragma unroll
        for (int nt = 0; nt < 8; nt++) {
            float2 p0, p1;
            p0.x = f32_to_tf32f(sc[nt][0]); p0.y = f32_to_tf32f(sc[nt][1]);
            p1.x = f32_to_tf32f(sc[nt][2]); p1.y = f32_to_tf32f(sc[nt][3]);
            *(float2*)&Psw[g       * PS_STRIDE + nt * 8 + 2 * tig] = p0;
            *(float2*)&Psw[(g + 8) * PS_STRIDE + nt * 8 + 2 * tig] = p1;
        }
        __syncwarp();

        // O += P V  (A from Psw: 4 LDS per kc, reused over 8 nt)
#pragma unroll
        for (int kc = 0; kc < 8; kc++) {
            int k0 = kc * 8 + tig;
            float a0 = Psw[g       * PS_STRIDE + k0];
            float a1 = Psw[(g + 8) * PS_STRIDE + k0];
            float a2 = Psw[g       * PS_STRIDE + k0 + 4];
            float a3 = Psw[(g + 8) * PS_STRIDE + k0 + 4];
#pragma unroll
            for (int nt = 0; nt < 8; nt++) {
                float b0 = Vs[k0       * VS_STRIDE + nt * 8 + g];
                float b1 = Vs[(k0 + 4) * VS_STRIDE + nt * 8 + g];
                mma_tf32_16x8x8(ov[nt], a0, a1, a2, a3, b0, b1);
            }
        }
        __syncwarp();
        __syncthreads();   // protect Ks/Vs before next tile's overwrite
    }

    // Epilogue: normalize, write rows qrow+g / qrow+g+8 to [B][S][H*hd]
    float inv0 = 1.0f / l0r;
    float inv1 = 1.0f / l1r;
    int s0 = qrow + g;
    int s1 = qrow + g + 8;
#pragma unroll
    for (int nt = 0; nt < 8; nt++) {
        int d = nt * 8 + 2 * tig;
        float2 v0, v1;
        v0.x = ov[nt][0] * inv0; v0.y = ov[nt][1] * inv0;
        v1.x = ov[nt][2] * inv1; v1.y = ov[nt][3] * inv1;
        *(float2*)&g_attn[((size_t)(b * SEQ + s0)) * DMODEL + h * HDIM + d] = v0;
        *(float2*)&g_attn[((size_t)(b * SEQ + s1)) * DMODEL + h * HDIM + d] = v1;
    }
}

// ---------------------------------------------------------------------------
// Launch
// ---------------------------------------------------------------------------
extern "C" void kernel_launch(void* const* d_in, const int* in_sizes, int n_in,
                              void* d_out, int out_size)
{
    const float* x      = (const float*)d_in[0];
    const float* w_qkv  = (const float*)d_in[1];
    const float* b_qkv  = (const float*)d_in[2];
    const float* w_proj = (const float*)d_in[3];
    const float* b_proj = (const float*)d_in[4];
    float* out = (float*)d_out;

    cudaFuncSetAttribute(flash_tc_kernel, cudaFuncAttributeMaxDynamicSharedMemorySize, FLASH_SMEM);

    gemm_tc_kernel<<<dim3(QKV_N / 128, MTOT / 128), 256>>>(x, w_qkv, b_qkv, nullptr, 0);
    flash_tc_kernel<<<dim3(SEQ / 128, NHEAD, BATCH), 256, FLASH_SMEM>>>();
    gemm_tc_kernel<<<dim3(DMODEL / 128, MTOT / 128), 256>>>(nullptr, w_proj, b_proj, out, 1);
}

// round 7
// speedup vs baseline: 3.5673x; 1.2876x over previous
#include <cuda_runtime.h>
#include <math.h>
#include <stdint.h>

// Problem constants
#define BATCH 2
#define SEQ   2048
#define DMODEL 1024
#define NHEAD 16
#define HDIM  64
#define MTOT  (BATCH*SEQ)            // 4096
#define QKV_N (3*DMODEL)             // 3072
#define GK    1024

// Scratch (allocation-free: __device__ globals)
__device__ float g_qkv[3u * 4194304u];   // [3][B][H][S][hd]
__device__ float g_attn[4194304u];       // [B][S][H*hd] == [4096][1024]

__device__ __forceinline__ float f32_to_tf32f(float x) {
    uint32_t r;
    asm("cvt.rna.tf32.f32 %0, %1;" : "=r"(r) : "f"(x));
    return __uint_as_float(r);
}

__device__ __forceinline__ void mma_tf32_16x8x8(float* c,
                                                float a0, float a1, float a2, float a3,
                                                float b0, float b1) {
    asm volatile(
        "mma.sync.aligned.m16n8k8.row.col.f32.tf32.tf32.f32 "
        "{%0,%1,%2,%3}, {%4,%5,%6,%7}, {%8,%9}, {%0,%1,%2,%3};"
        : "+f"(c[0]), "+f"(c[1]), "+f"(c[2]), "+f"(c[3])
        : "r"(__float_as_uint(a0)), "r"(__float_as_uint(a1)),
          "r"(__float_as_uint(a2)), "r"(__float_as_uint(a3)),
          "r"(__float_as_uint(b0)), "r"(__float_as_uint(b1)));
}

// ---------------------------------------------------------------------------
// tf32 mma.sync GEMM — identical to R6 except __launch_bounds__(256, 2)
// to cap regs at 128 and get 2 CTAs/SM (was 140 regs -> occ 12%).
// ---------------------------------------------------------------------------
#define LDS_STRIDE 20

__global__ __launch_bounds__(256, 2) void gemm_tc_kernel(
    const float* __restrict__ A_arg,
    const float* __restrict__ W,
    const float* __restrict__ bias,
    float* __restrict__ out,
    int mode)
{
    __shared__ float As[2][128 * LDS_STRIDE];
    __shared__ float Bs[2][128 * LDS_STRIDE];

    const float* A = (A_arg != nullptr) ? A_arg : (const float*)g_attn;

    int tid  = threadIdx.x;
    int wid  = tid >> 5;
    int lane = tid & 31;
    int wm   = wid >> 2;
    int wn   = wid & 3;
    int g    = lane >> 2;
    int tig  = lane & 3;

    int m0 = blockIdx.y * 128;
    int n0 = blockIdx.x * 128;

    int ar0 = tid >> 2;
    int ar1 = ar0 + 64;
    int ac  = (tid & 3) * 4;

    const float* Ab = A + (size_t)m0 * GK + ac;
    const float* Wb = W + (size_t)n0 * GK + ac;

    float c[4][4][4];
#pragma unroll
    for (int i = 0; i < 4; i++)
#pragma unroll
        for (int j = 0; j < 4; j++)
#pragma unroll
            for (int q = 0; q < 4; q++) c[i][j][q] = 0.f;

    {
        float4 a0 = *(const float4*)(Ab + (size_t)ar0 * GK);
        float4 a1 = *(const float4*)(Ab + (size_t)ar1 * GK);
        float4 b0 = *(const float4*)(Wb + (size_t)ar0 * GK);
        float4 b1 = *(const float4*)(Wb + (size_t)ar1 * GK);
        float* as = As[0]; float* bs = Bs[0];
        as[ar0 * LDS_STRIDE + ac + 0] = f32_to_tf32f(a0.x);
        as[ar0 * LDS_STRIDE + ac + 1] = f32_to_tf32f(a0.y);
        as[ar0 * LDS_STRIDE + ac + 2] = f32_to_tf32f(a0.z);
        as[ar0 * LDS_STRIDE + ac + 3] = f32_to_tf32f(a0.w);
        as[ar1 * LDS_STRIDE + ac + 0] = f32_to_tf32f(a1.x);
        as[ar1 * LDS_STRIDE + ac + 1] = f32_to_tf32f(a1.y);
        as[ar1 * LDS_STRIDE + ac + 2] = f32_to_tf32f(a1.z);
        as[ar1 * LDS_STRIDE + ac + 3] = f32_to_tf32f(a1.w);
        bs[ar0 * LDS_STRIDE + ac + 0] = f32_to_tf32f(b0.x);
        bs[ar0 * LDS_STRIDE + ac + 1] = f32_to_tf32f(b0.y);
        bs[ar0 * LDS_STRIDE + ac + 2] = f32_to_tf32f(b0.z);
        bs[ar0 * LDS_STRIDE + ac + 3] = f32_to_tf32f(b0.w);
        bs[ar1 * LDS_STRIDE + ac + 0] = f32_to_tf32f(b1.x);
        bs[ar1 * LDS_STRIDE + ac + 1] = f32_to_tf32f(b1.y);
        bs[ar1 * LDS_STRIDE + ac + 2] = f32_to_tf32f(b1.z);
        bs[ar1 * LDS_STRIDE + ac + 3] = f32_to_tf32f(b1.w);
    }
    __syncthreads();

    const int NT = GK / 16;
    for (int kt = 0; kt < NT; kt++) {
        int cur = kt & 1;
        float4 na0, na1, nb0, nb1;
        if (kt < NT - 1) {
            int ko = (kt + 1) * 16;
            na0 = *(const float4*)(Ab + (size_t)ar0 * GK + ko);
            na1 = *(const float4*)(Ab + (size_t)ar1 * GK + ko);
            nb0 = *(const float4*)(Wb + (size_t)ar0 * GK + ko);
            nb1 = *(const float4*)(Wb + (size_t)ar1 * GK + ko);
        }

        const float* as = As[cur];
        const float* bs = Bs[cur];
#pragma unroll
        for (int k8 = 0; k8 < 2; k8++) {
            int kc = k8 * 8 + tig;
            float af[4][4], bf[4][2];
#pragma unroll
            for (int mt = 0; mt < 4; mt++) {
                int r = wm * 64 + mt * 16 + g;
                af[mt][0] = as[(r + 0) * LDS_STRIDE + kc];
                af[mt][1] = as[(r + 8) * LDS_STRIDE + kc];
                af[mt][2] = as[(r + 0) * LDS_STRIDE + kc + 4];
                af[mt][3] = as[(r + 8) * LDS_STRIDE + kc + 4];
            }
#pragma unroll
            for (int nt = 0; nt < 4; nt++) {
                int r = wn * 32 + nt * 8 + g;
                bf[nt][0] = bs[r * LDS_STRIDE + kc];
                bf[nt][1] = bs[r * LDS_STRIDE + kc + 4];
            }
#pragma unroll
            for (int mt = 0; mt < 4; mt++)
#pragma unroll
                for (int nt = 0; nt < 4; nt++)
                    mma_tf32_16x8x8(c[mt][nt],
                                    af[mt][0], af[mt][1], af[mt][2], af[mt][3],
                                    bf[nt][0], bf[nt][1]);
        }
        __syncthreads();

        if (kt < NT - 1) {
            float* asn = As[cur ^ 1]; float* bsn = Bs[cur ^ 1];
            asn[ar0 * LDS_STRIDE + ac + 0] = f32_to_tf32f(na0.x);
            asn[ar0 * LDS_STRIDE + ac + 1] = f32_to_tf32f(na0.y);
            asn[ar0 * LDS_STRIDE + ac + 2] = f32_to_tf32f(na0.z);
            asn[ar0 * LDS_STRIDE + ac + 3] = f32_to_tf32f(na0.w);
            asn[ar1 * LDS_STRIDE + ac + 0] = f32_to_tf32f(na1.x);
            asn[ar1 * LDS_STRIDE + ac + 1] = f32_to_tf32f(na1.y);
            asn[ar1 * LDS_STRIDE + ac + 2] = f32_to_tf32f(na1.z);
            asn[ar1 * LDS_STRIDE + ac + 3] = f32_to_tf32f(na1.w);
            bsn[ar0 * LDS_STRIDE + ac + 0] = f32_to_tf32f(nb0.x);
            bsn[ar0 * LDS_STRIDE + ac + 1] = f32_to_tf32f(nb0.y);
            bsn[ar0 * LDS_STRIDE + ac + 2] = f32_to_tf32f(nb0.z);
            bsn[ar0 * LDS_STRIDE + ac + 3] = f32_to_tf32f(nb0.w);
            bsn[ar1 * LDS_STRIDE + ac + 0] = f32_to_tf32f(nb1.x);
            bsn[ar1 * LDS_STRIDE + ac + 1] = f32_to_tf32f(nb1.y);
            bsn[ar1 * LDS_STRIDE + ac + 2] = f32_to_tf32f(nb1.z);
            bsn[ar1 * LDS_STRIDE + ac + 3] = f32_to_tf32f(nb1.w);
            __syncthreads();
        }
    }

#pragma unroll
    for (int mt = 0; mt < 4; mt++) {
#pragma unroll
        for (int half = 0; half < 2; half++) {
            int m = m0 + wm * 64 + mt * 16 + g + half * 8;
            int b = m >> 11;
            int s = m & 2047;
#pragma unroll
            for (int nt = 0; nt < 4; nt++) {
                int n = n0 + wn * 32 + nt * 8 + 2 * tig;
                float2 v;
                v.x = c[mt][nt][half * 2 + 0] + bias[n + 0];
                v.y = c[mt][nt][half * 2 + 1] + bias[n + 1];
                if (mode == 0) {
                    int which = n >> 10;
                    int rr = n & 1023;
                    int h = rr >> 6;
                    int d = rr & 63;
                    *(float2*)&g_qkv[(size_t)which * 4194304u +
                                     ((size_t)((b << 4) + h) * SEQ + s) * HDIM + d] = v;
                } else {
                    *(float2*)&out[(size_t)m * DMODEL + n] = v;
                }
            }
        }
    }
}

// ---------------------------------------------------------------------------
// Flash attention with tf32 mma.sync — identical to R6 except
// __launch_bounds__(256, 2) for 2 CTAs/SM.
// ---------------------------------------------------------------------------
#define KS_STRIDE 68
#define VS_STRIDE 72
#define PS_STRIDE 68
#define FLASH_SMEM ((64*KS_STRIDE + 64*VS_STRIDE + 128*PS_STRIDE) * 4)

__global__ __launch_bounds__(256, 2) void flash_tc_kernel()
{
    extern __shared__ float smf[];
    float* Ks = smf;                                    // [64][KS_STRIDE]
    float* Vs = smf + 64 * KS_STRIDE;                   // [64][VS_STRIDE]
    float* Ps = smf + 64 * KS_STRIDE + 64 * VS_STRIDE;  // [128][PS_STRIDE]

    int tid  = threadIdx.x;
    int w    = tid >> 5;
    int lane = tid & 31;
    int g    = lane >> 2;          // 0..7
    int tig  = lane & 3;           // 0..3

    int q0 = blockIdx.x * 128;
    int h  = blockIdx.y;
    int b  = blockIdx.z;

    const float scale = 0.125f;    // 1/sqrt(64)

    const float* Qg = g_qkv + 0u * 4194304u + (size_t)((b << 4) + h) * SEQ * HDIM;
    const float* Kg = g_qkv + 1u * 4194304u + (size_t)((b << 4) + h) * SEQ * HDIM;
    const float* Vg = g_qkv + 2u * 4194304u + (size_t)((b << 4) + h) * SEQ * HDIM;

    // Q fragments, register-resident for whole kernel (scale + tf32 folded)
    int qrow = q0 + w * 16;
    float qf[8][4];
#pragma unroll
    for (int kc = 0; kc < 8; kc++) {
        int d0 = kc * 8 + tig;
        qf[kc][0] = f32_to_tf32f(Qg[(size_t)(qrow + g)     * HDIM + d0]     * scale);
        qf[kc][1] = f32_to_tf32f(Qg[(size_t)(qrow + g + 8) * HDIM + d0]     * scale);
        qf[kc][2] = f32_to_tf32f(Qg[(size_t)(qrow + g)     * HDIM + d0 + 4] * scale);
        qf[kc][3] = f32_to_tf32f(Qg[(size_t)(qrow + g + 8) * HDIM + d0 + 4] * scale);
    }

    float m0r = -1e30f, m1r = -1e30f, l0r = 0.f, l1r = 0.f;
    float ov[8][4];
#pragma unroll
    for (int nt = 0; nt < 8; nt++)
#pragma unroll
        for (int q = 0; q < 4; q++) ov[nt][q] = 0.f;

    float* Psw = Ps + w * 16 * PS_STRIDE;   // per-warp private slab

    for (int kt = 0; kt < SEQ / 64; kt++) {
        const float* Kt = Kg + (size_t)kt * 64 * HDIM;
        const float* Vt = Vg + (size_t)kt * 64 * HDIM;

        // Load + convert K and V tiles (aligned float4 paths)
#pragma unroll
        for (int it = 0; it < 4; it++) {
            int j   = tid + it * 256;          // float4 index 0..1023
            int row = j >> 4;
            int c4  = (j & 15) << 2;
            float4 kv = *(const float4*)(Kt + row * HDIM + c4);
            float4 vv = *(const float4*)(Vt + row * HDIM + c4);
            float4 kc4, vc4;
            kc4.x = f32_to_tf32f(kv.x); kc4.y = f32_to_tf32f(kv.y);
            kc4.z = f32_to_tf32f(kv.z); kc4.w = f32_to_tf32f(kv.w);
            vc4.x = f32_to_tf32f(vv.x); vc4.y = f32_to_tf32f(vv.y);
            vc4.z = f32_to_tf32f(vv.z); vc4.w = f32_to_tf32f(vv.w);
            *(float4*)&Ks[row * KS_STRIDE + c4] = kc4;
            *(float4*)&Vs[row * VS_STRIDE + c4] = vc4;
        }
        __syncthreads();

        // S = Q K^T  (per warp: 16 rows x 64 keys, 8 nt x 8 kc mma)
        float sc[8][4];
#pragma unroll
        for (int nt = 0; nt < 8; nt++)
#pragma unroll
            for (int q = 0; q < 4; q++) sc[nt][q] = 0.f;
#pragma unroll
        for (int kc = 0; kc < 8; kc++) {
            int d0 = kc * 8 + tig;
#pragma unroll
            for (int nt = 0; nt < 8; nt++) {
                int key = nt * 8 + g;
                float b0 = Ks[key * KS_STRIDE + d0];
                float b1 = Ks[key * KS_STRIDE + d0 + 4];
                mma_tf32_16x8x8(sc[nt], qf[kc][0], qf[kc][1], qf[kc][2], qf[kc][3], b0, b1);
            }
        }

        // Online softmax. Row r0 = qrow+g holds sc[nt][0],sc[nt][1];
        // row r1 = qrow+g+8 holds sc[nt][2],sc[nt][3]. Quad lanes (tig) share rows.
        float rm0 = -1e30f, rm1 = -1e30f;
#pragma unroll
        for (int nt = 0; nt < 8; nt++) {
            rm0 = fmaxf(rm0, fmaxf(sc[nt][0], sc[nt][1]));
            rm1 = fmaxf(rm1, fmaxf(sc[nt][2], sc[nt][3]));
        }
        rm0 = fmaxf(rm0, __shfl_xor_sync(0xffffffffu, rm0, 1));
        rm0 = fmaxf(rm0, __shfl_xor_sync(0xffffffffu, rm0, 2));
        rm1 = fmaxf(rm1, __shfl_xor_sync(0xffffffffu, rm1, 1));
        rm1 = fmaxf(rm1, __shfl_xor_sync(0xffffffffu, rm1, 2));

        float nm0 = fmaxf(m0r, rm0);
        float nm1 = fmaxf(m1r, rm1);
        float alpha0 = __expf(m0r - nm0);
        float alpha1 = __expf(m1r - nm1);
        m0r = nm0; m1r = nm1;

        float rs0 = 0.f, rs1 = 0.f;
#pragma unroll
        for (int nt = 0; nt < 8; nt++) {
            sc[nt][0] = __expf(sc[nt][0] - nm0);
            sc[nt][1] = __expf(sc[nt][1] - nm0);
            sc[nt][2] = __expf(sc[nt][2] - nm1);
            sc[nt][3] = __expf(sc[nt][3] - nm1);
            rs0 += sc[nt][0] + sc[nt][1];
            rs1 += sc[nt][2] + sc[nt][3];
        }
        rs0 += __shfl_xor_sync(0xffffffffu, rs0, 1);
        rs0 += __shfl_xor_sync(0xffffffffu, rs0, 2);
        rs1 += __shfl_xor_sync(0xffffffffu, rs1, 1);
        rs1 += __shfl_xor_sync(0xffffffffu, rs1, 2);
        l0r = l0r * alpha0 + rs0;
        l1r = l1r * alpha1 + rs1;

        // Rescale O accumulators
#pragma unroll
        for (int nt = 0; nt < 8; nt++) {
            ov[nt][0] *= alpha0; ov[nt][1] *= alpha0;
            ov[nt][2] *= alpha1; ov[nt][3] *= alpha1;
        }

        // Stage P (tf32-rounded) into per-warp slab; only this warp touches it.
#pragma unroll
        for (int nt = 0; nt < 8; nt++) {
            float2 p0, p1;
            p0.x = f32_to_tf32f(sc[nt][0]); p0.y = f32_to_tf32f(sc[nt][1]);
            p1.x = f32_to_tf32f(sc[nt][2]); p1.y = f32_to_tf32f(sc[nt][3]);
            *(float2*)&Psw[g       * PS_STRIDE + nt * 8 + 2 * tig] = p0;
            *(float2*)&Psw[(g + 8) * PS_STRIDE + nt * 8 + 2 * tig] = p1;
        }
        __syncwarp();

        // O += P V  (A from Psw: 4 LDS per kc, reused over 8 nt)
#pragma unroll
        for (int kc = 0; kc < 8; kc++) {
            int k0 = kc * 8 + tig;
            float a0 = Psw[g       * PS_STRIDE + k0];
            float a1 = Psw[(g + 8) * PS_STRIDE + k0];
            float a2 = Psw[g       * PS_STRIDE + k0 + 4];
            float a3 = Psw[(g + 8) * PS_STRIDE + k0 + 4];
#pragma unroll
            for (int nt = 0; nt < 8; nt++) {
                float b0 = Vs[k0       * VS_STRIDE + nt * 8 + g];
                float b1 = Vs[(k0 + 4) * VS_STRIDE + nt * 8 + g];
                mma_tf32_16x8x8(ov[nt], a0, a1, a2, a3, b0, b1);
            }
        }
        __syncwarp();
        __syncthreads();   // protect Ks/Vs before next tile's overwrite
    }

    // Epilogue: normalize, write rows qrow+g / qrow+g+8 to [B][S][H*hd]
    float inv0 = 1.0f / l0r;
    float inv1 = 1.0f / l1r;
    int s0 = qrow + g;
    int s1 = qrow + g + 8;
#pragma unroll
    for (int nt = 0; nt < 8; nt++) {
        int d = nt * 8 + 2 * tig;
        float2 v0, v1;
        v0.x = ov[nt][0] * inv0; v0.y = ov[nt][1] * inv0;
        v1.x = ov[nt][2] * inv1; v1.y = ov[nt][3] * inv1;
        *(float2*)&g_attn[((size_t)(b * SEQ + s0)) * DMODEL + h * HDIM + d] = v0;
        *(float2*)&g_attn[((size_t)(b * SEQ + s1)) * DMODEL + h * HDIM + d] = v1;
    }
}

// ---------------------------------------------------------------------------
// Launch
// ---------------------------------------------------------------------------
extern "C" void kernel_launch(void* const* d_in, const int* in_sizes, int n_in,
                              void* d_out, int out_size)
{
    const float* x      = (const float*)d_in[0];
    const float* w_qkv  = (const float*)d_in[1];
    const float* b_qkv  = (const float*)d_in[2];
    const float* w_proj = (const float*)d_in[3];
    const float* b_proj = (const float*)d_in[4];
    float* out = (float*)d_out;

    cudaFuncSetAttribute(flash_tc_kernel, cudaFuncAttributeMaxDynamicSharedMemorySize, FLASH_SMEM);

    gemm_tc_kernel<<<dim3(QKV_N / 128, MTOT / 128), 256>>>(x, w_qkv, b_qkv, nullptr, 0);
    flash_tc_kernel<<<dim3(SEQ / 128, NHEAD, BATCH), 256, FLASH_SMEM>>>();
    gemm_tc_kernel<<<dim3(DMODEL / 128, MTOT / 128), 256>>>(nullptr, w_proj, b_proj, out, 1);
}